// round 7
// baseline (speedup 1.0000x reference)
#include <cuda_runtime.h>
#include <cuda_fp16.h>
#include <cstdint>

// ---------------------------------------------------------------------------
// Problem constants
// ---------------------------------------------------------------------------
#define BATCH 16
#define SEQ   1024
#define VDIM  1024
#define TDIM  768
#define HDIM  512
#define MTOT  (BATCH*SEQ)

// ---------------------------------------------------------------------------
// Scratch (device globals — allocation is forbidden)
// ---------------------------------------------------------------------------
__device__ __align__(256) __half g_vis_h[(size_t)MTOT*VDIM];
__device__ __align__(256) __half g_txt_h[(size_t)MTOT*TDIM];
__device__ __align__(256) __half g_Wv_h[(size_t)HDIM*VDIM];
__device__ __align__(256) __half g_Wv_l[(size_t)HDIM*VDIM];
__device__ __align__(256) __half g_Wt_h[(size_t)HDIM*TDIM];
__device__ __align__(256) __half g_Wt_l[(size_t)HDIM*TDIM];
__device__ __align__(256) __half g_v_h[(size_t)MTOT*HDIM];
__device__ __align__(256) __half g_v_l[(size_t)MTOT*HDIM];
__device__ __align__(256) __half g_t_h[(size_t)MTOT*HDIM];
__device__ __align__(256) __half g_t_l[(size_t)MTOT*HDIM];
__device__ float g_rvn[MTOT], g_rtn[MTOT];   // RECIPROCAL norms

// ---------------------------------------------------------------------------
// Helpers
// ---------------------------------------------------------------------------
__device__ __forceinline__ uint32_t smem_u32(const void* p) {
    uint32_t a;
    asm("{ .reg .u64 t; cvta.to.shared.u64 t, %1; cvt.u32.u64 %0, t; }"
        : "=r"(a) : "l"(p));
    return a;
}

__device__ __forceinline__ void cp_async16(uint32_t d, const void* g) {
    asm volatile("cp.async.cg.shared.global [%0], [%1], 16;\n"
                 :: "r"(d), "l"(__cvta_generic_to_global(g)) : "memory");
}
__device__ __forceinline__ void cp_commit() {
    asm volatile("cp.async.commit_group;\n" ::: "memory");
}
template <int N>
__device__ __forceinline__ void cp_wait() {
    asm volatile("cp.async.wait_group %0;\n" :: "n"(N) : "memory");
}

__device__ __forceinline__ void ldsm4(uint32_t* r, uint32_t a) {
    asm volatile("ldmatrix.sync.aligned.m8n8.x4.shared.b16 {%0,%1,%2,%3}, [%4];\n"
                 : "=r"(r[0]), "=r"(r[1]), "=r"(r[2]), "=r"(r[3]) : "r"(a));
}

__device__ __forceinline__ void mma16816(float* c, const uint32_t* a,
                                         const uint32_t* b) {
    asm volatile(
        "mma.sync.aligned.m16n8k16.row.col.f32.f16.f16.f32 "
        "{%0,%1,%2,%3}, {%4,%5,%6,%7}, {%8,%9}, {%0,%1,%2,%3};\n"
        : "+f"(c[0]), "+f"(c[1]), "+f"(c[2]), "+f"(c[3])
        : "r"(a[0]), "r"(a[1]), "r"(a[2]), "r"(a[3]), "r"(b[0]), "r"(b[1]));
}

__device__ __forceinline__ uint32_t pack2h(__half a, __half b) {
    __half2 t = __halves2half2(a, b);
    return *reinterpret_cast<uint32_t*>(&t);
}

// Swizzled smem offset: 64B rows (32 halfs), 4 x 16B chunks per row.
__device__ __forceinline__ uint32_t swoff(int row, int chunk) {
    int c2 = (chunk ^ (row & 3) ^ ((row >> 2) & 1)) & 3;
    return (uint32_t)(row * 64 + (c2 << 4));
}

// ---------------------------------------------------------------------------
// fp16 split-emulation mma.sync GEMM:  C[m,n] = sum_k A[m,k]*B[n,k]
// NTERMS==1:  D = Ah*Bh                  (plain fp16)
// NTERMS==2:  D = Ah*Bh + Ah*Bl          (B carried to ~fp32 precision)
// Block 128x256, BK=32, 8 warps (2x4), warp tile 64x64, STAGES-deep cp.async.
// MODE 0: epilogue adds bias[n], splits result to fp16 hi/lo arrays (ld=ldOut)
// MODE 1: epilogue multiplies by rvn[m]*rtn[n] (reciprocal norms), fp32 out
// ---------------------------------------------------------------------------
template <int NTERMS, int STAGES, int MODE>
__global__ void __launch_bounds__(256, 1) mma_gemm(
    const __half* __restrict__ Ahp,
    const __half* __restrict__ Bhp, const __half* __restrict__ Blp,
    int K, int ldOut, long sA, long sB, long sC,
    const float* __restrict__ p1,   // MODE0: bias   MODE1: rvn
    const float* __restrict__ p2,   // MODE1: rtn
    float* __restrict__ Cf, __half* __restrict__ Ch, __half* __restrict__ Cl)
{
    // A tile 128x32 = 8 KB; each B tile 256x32 = 16 KB
    constexpr int STG_BYTES = (NTERMS == 2) ? 40960 : 24576;
    constexpr uint32_t OFF_BH = 8192, OFF_BL = 24576;

    extern __shared__ __align__(16) char smem[];

    const int tid  = threadIdx.x;
    const int lane = tid & 31;
    const int wid  = tid >> 5;
    const int wm   = wid >> 2;        // 0..1 : 64-row half
    const int wn   = wid & 3;         // 0..3 : 64-col quarter
    const int z    = blockIdx.z;
    const int m0   = blockIdx.y * 128;
    const int n0   = blockIdx.x * 256;

    const __half* Abh = Ahp + (long)z * sA + (long)m0 * K;
    const __half* Bbh = Bhp + (long)z * sB + (long)n0 * K;
    const __half* Bbl = (NTERMS == 2) ? (Blp + (long)z * sB + (long)n0 * K) : nullptr;

    const uint32_t smb = smem_u32(smem);

    auto load_stage = [&](int kt, int slot) {
        const int k0 = kt * 32;
        const uint32_t sb = smb + slot * STG_BYTES;
        // A: 128 rows x 4 chunks = 512
        #pragma unroll
        for (int h = 0; h < 2; h++) {
            int idx = tid + h * 256;
            int row = idx >> 2, kc = idx & 3;
            cp_async16(sb + swoff(row, kc), Abh + (long)row * K + k0 + kc * 8);
        }
        // B: 256 rows x 4 chunks = 1024 (per term)
        #pragma unroll
        for (int h = 0; h < 4; h++) {
            int idx = tid + h * 256;
            int row = idx >> 2, kc = idx & 3;
            uint32_t off = swoff(row, kc);
            long g = (long)row * K + k0 + kc * 8;
            cp_async16(sb + OFF_BH + off, Bbh + g);
            if (NTERMS == 2) cp_async16(sb + OFF_BL + off, Bbl + g);
        }
    };

    #pragma unroll
    for (int s = 0; s < STAGES - 1; s++) { load_stage(s, s); cp_commit(); }

    float acc[4][8][4];
    #pragma unroll
    for (int i = 0; i < 4; i++)
        #pragma unroll
        for (int j = 0; j < 8; j++)
            #pragma unroll
            for (int q = 0; q < 4; q++) acc[i][j][q] = 0.0f;

    const int a_r = lane & 15;
    const int a_c = lane >> 4;
    const int b_r = (lane & 7) | ((lane & 16) >> 1);
    const int b_c = (lane >> 3) & 1;

    const int T = K / 32;
    for (int kt = 0; kt < T; kt++) {
        cp_wait<STAGES - 2>();
        __syncthreads();
        if (kt + STAGES - 1 < T) load_stage(kt + STAGES - 1, (kt + STAGES - 1) % STAGES);
        cp_commit();

        const uint32_t st = smb + (kt % STAGES) * STG_BYTES;

        #pragma unroll
        for (int s2 = 0; s2 < 2; s2++) {
            // A fragments: 64 rows
            uint32_t afr[4][4];
            #pragma unroll
            for (int i = 0; i < 4; i++)
                ldsm4(afr[i], st + swoff(wm * 64 + i * 16 + a_r, s2 * 2 + a_c));
            // Bh fragments: 64 cols
            uint32_t bf[8][2];
            #pragma unroll
            for (int jp = 0; jp < 4; jp++) {
                uint32_t r4[4];
                ldsm4(r4, st + OFF_BH + swoff(wn * 64 + jp * 16 + b_r, s2 * 2 + b_c));
                bf[jp*2][0] = r4[0]; bf[jp*2][1] = r4[1];
                bf[jp*2+1][0] = r4[2]; bf[jp*2+1][1] = r4[3];
            }
            #pragma unroll
            for (int i = 0; i < 4; i++)
                #pragma unroll
                for (int j = 0; j < 8; j++)
                    mma16816(acc[i][j], afr[i], bf[j]);
            // Bl fragments (reuse A fragments, overwrite bf)
            if (NTERMS == 2) {
                #pragma unroll
                for (int jp = 0; jp < 4; jp++) {
                    uint32_t r4[4];
                    ldsm4(r4, st + OFF_BL + swoff(wn * 64 + jp * 16 + b_r, s2 * 2 + b_c));
                    bf[jp*2][0] = r4[0]; bf[jp*2][1] = r4[1];
                    bf[jp*2+1][0] = r4[2]; bf[jp*2+1][1] = r4[3];
                }
                #pragma unroll
                for (int i = 0; i < 4; i++)
                    #pragma unroll
                    for (int j = 0; j < 8; j++)
                        mma16816(acc[i][j], afr[i], bf[j]);
            }
        }
    }

    // ---------------- epilogue ----------------
    if (MODE == 0) {
        #pragma unroll
        for (int i = 0; i < 4; i++) {
            long r0 = m0 + wm * 64 + i * 16 + (lane >> 2);
            #pragma unroll
            for (int j = 0; j < 8; j++) {
                int cc = n0 + wn * 64 + j * 8 + 2 * (lane & 3);
                float bx = p1[cc], by = p1[cc + 1];
                #pragma unroll
                for (int h = 0; h < 2; h++) {
                    long row = r0 + h * 8;
                    float x = acc[i][j][h*2 + 0] + bx;
                    float y = acc[i][j][h*2 + 1] + by;
                    __half hx = __float2half_rn(x);
                    __half hy = __float2half_rn(y);
                    uint32_t hp = pack2h(hx, hy);
                    uint32_t lp = pack2h(__float2half_rn(x - __half2float(hx)),
                                         __float2half_rn(y - __half2float(hy)));
                    *reinterpret_cast<uint32_t*>(Ch + row * ldOut + cc) = hp;
                    *reinterpret_cast<uint32_t*>(Cl + row * ldOut + cc) = lp;
                }
            }
        }
    } else {
        #pragma unroll
        for (int i = 0; i < 4; i++) {
            int r0 = m0 + wm * 64 + i * 16 + (lane >> 2);
            float rv0 = p1[z * SEQ + r0];         // reciprocal norms
            float rv1 = p1[z * SEQ + r0 + 8];
            #pragma unroll
            for (int j = 0; j < 8; j++) {
                int cc = n0 + wn * 64 + j * 8 + 2 * (lane & 3);
                float rt0 = p2[z * SEQ + cc], rt1 = p2[z * SEQ + cc + 1];
                float2 o0, o1;
                o0.x = acc[i][j][0] * (rv0 * rt0);
                o0.y = acc[i][j][1] * (rv0 * rt1);
                o1.x = acc[i][j][2] * (rv1 * rt0);
                o1.y = acc[i][j][3] * (rv1 * rt1);
                float* p = Cf + z * sC + (long)r0 * ldOut + cc;
                *reinterpret_cast<float2*>(p)              = o0;
                *reinterpret_cast<float2*>(p + 8L * ldOut) = o1;
            }
        }
    }
}

// ---------------------------------------------------------------------------
// fp32 -> fp16 (hi, lo) split, vectorized x4 (weights)
// ---------------------------------------------------------------------------
__global__ void split_kernel(const float4* __restrict__ in,
                             uint2* __restrict__ h, uint2* __restrict__ l, int n4)
{
    int i = blockIdx.x * blockDim.x + threadIdx.x;
    if (i >= n4) return;
    float4 v = in[i];
    __half h0 = __float2half_rn(v.x), h1 = __float2half_rn(v.y);
    __half h2 = __float2half_rn(v.z), h3 = __float2half_rn(v.w);
    h[i] = make_uint2(pack2h(h0, h1), pack2h(h2, h3));
    l[i] = make_uint2(pack2h(__float2half_rn(v.x - __half2float(h0)),
                             __float2half_rn(v.y - __half2float(h1))),
                      pack2h(__float2half_rn(v.z - __half2float(h2)),
                             __float2half_rn(v.w - __half2float(h3))));
}

// ---------------------------------------------------------------------------
// fp32 -> fp16 hi only, vectorized x4 (activations)
// ---------------------------------------------------------------------------
__global__ void cvt_kernel(const float4* __restrict__ in,
                           uint2* __restrict__ h, int n4)
{
    int i = blockIdx.x * blockDim.x + threadIdx.x;
    if (i >= n4) return;
    float4 v = in[i];
    h[i] = make_uint2(pack2h(__float2half_rn(v.x), __float2half_rn(v.y)),
                      pack2h(__float2half_rn(v.z), __float2half_rn(v.w)));
}

// ---------------------------------------------------------------------------
// Reciprocal row L2 norms from split fp16 (x = hi + lo); one warp per row.
// ---------------------------------------------------------------------------
__global__ void norms_kernel(const __half* __restrict__ H,
                             const __half* __restrict__ L,
                             float* __restrict__ out)
{
    int row  = blockIdx.x * blockDim.y + threadIdx.y;
    int lane = threadIdx.x;
    const __half* hi = H + (long)row * HDIM;
    const __half* lo = L + (long)row * HDIM;
    float s = 0.0f;
    #pragma unroll
    for (int i = lane * 4; i < HDIM; i += 128) {
        uint2 hu = *reinterpret_cast<const uint2*>(hi + i);
        uint2 lu = *reinterpret_cast<const uint2*>(lo + i);
        __half2 h01 = *reinterpret_cast<const __half2*>(&hu.x);
        __half2 h23 = *reinterpret_cast<const __half2*>(&hu.y);
        __half2 l01 = *reinterpret_cast<const __half2*>(&lu.x);
        __half2 l23 = *reinterpret_cast<const __half2*>(&lu.y);
        float x0 = __low2float(h01)  + __low2float(l01);
        float x1 = __high2float(h01) + __high2float(l01);
        float x2 = __low2float(h23)  + __low2float(l23);
        float x3 = __high2float(h23) + __high2float(l23);
        s += x0*x0 + x1*x1 + x2*x2 + x3*x3;
    }
    #pragma unroll
    for (int o = 16; o > 0; o >>= 1) s += __shfl_xor_sync(0xffffffffu, s, o);
    if (lane == 0) out[row] = rsqrtf(fmaxf(s, 1e-16f));
}

// ---------------------------------------------------------------------------
extern "C" void kernel_launch(void* const* d_in, const int* in_sizes, int n_in,
                              void* d_out, int out_size)
{
    const float* vis = (const float*)d_in[0];   // [16,1024,1024]
    const float* txt = (const float*)d_in[1];   // [16,1024,768]
    const float* Wv  = (const float*)d_in[2];   // [512,1024]
    const float* bv  = (const float*)d_in[3];   // [512]
    const float* Wt  = (const float*)d_in[4];   // [512,768]
    const float* bt  = (const float*)d_in[5];   // [512]
    float* out = (float*)d_out;                 // [16,1024,1024]

    __half *vis_h, *txt_h, *Wv_h, *Wv_l, *Wt_h, *Wt_l;
    __half *v_h, *v_l, *t_h, *t_l;
    float *rvn, *rtn;
    cudaGetSymbolAddress((void**)&vis_h, g_vis_h);
    cudaGetSymbolAddress((void**)&txt_h, g_txt_h);
    cudaGetSymbolAddress((void**)&Wv_h,  g_Wv_h);
    cudaGetSymbolAddress((void**)&Wv_l,  g_Wv_l);
    cudaGetSymbolAddress((void**)&Wt_h,  g_Wt_h);
    cudaGetSymbolAddress((void**)&Wt_l,  g_Wt_l);
    cudaGetSymbolAddress((void**)&v_h,   g_v_h);
    cudaGetSymbolAddress((void**)&v_l,   g_v_l);
    cudaGetSymbolAddress((void**)&t_h,   g_t_h);
    cudaGetSymbolAddress((void**)&t_l,   g_t_l);
    cudaGetSymbolAddress((void**)&rvn,   g_rvn);
    cudaGetSymbolAddress((void**)&rtn,   g_rtn);

    const int SMEM_P = 3 * 40960;   // proj: 2-term, 3 stages (120 KB)
    const int SMEM_D = 4 * 24576;   // dots: 1-term, 4 stages (96 KB)
    (void)cudaFuncSetAttribute((const void*)mma_gemm<2,3,0>,
                               cudaFuncAttributeMaxDynamicSharedMemorySize, SMEM_P);
    (void)cudaFuncSetAttribute((const void*)mma_gemm<1,4,1>,
                               cudaFuncAttributeMaxDynamicSharedMemorySize, SMEM_D);

    // 1) Convert activations to fp16 (hi only); split weights to hi/lo
    {
        int n4;
        n4 = MTOT * (VDIM/4);
        cvt_kernel<<<(n4+255)/256, 256>>>((const float4*)vis, (uint2*)vis_h, n4);
        n4 = MTOT * (TDIM/4);
        cvt_kernel<<<(n4+255)/256, 256>>>((const float4*)txt, (uint2*)txt_h, n4);
        n4 = HDIM * (VDIM/4);
        split_kernel<<<(n4+255)/256, 256>>>((const float4*)Wv, (uint2*)Wv_h, (uint2*)Wv_l, n4);
        n4 = HDIM * (TDIM/4);
        split_kernel<<<(n4+255)/256, 256>>>((const float4*)Wt, (uint2*)Wt_h, (uint2*)Wt_l, n4);
    }

    // 2) Projections (2-term fp16): Ah . (Wh + Wl) -> fp16 hi/lo [16384,512]
    {
        dim3 grid(HDIM/256, MTOT/128, 1);
        mma_gemm<2,3,0><<<grid, 256, SMEM_P>>>(vis_h, Wv_h, Wv_l,
                                               VDIM, HDIM, 0, 0, 0,
                                               bv, nullptr, nullptr, v_h, v_l);
        mma_gemm<2,3,0><<<grid, 256, SMEM_P>>>(txt_h, Wt_h, Wt_l,
                                               TDIM, HDIM, 0, 0, 0,
                                               bt, nullptr, nullptr, t_h, t_l);
    }

    // 3) Reciprocal row norms (from hi+lo, ~fp32-accurate)
    {
        dim3 blk(32, 8), grid(MTOT/8);
        norms_kernel<<<grid, blk>>>(v_h, v_l, rvn);
        norms_kernel<<<grid, blk>>>(t_h, t_l, rtn);
    }

    // 4) Batched cosine GEMM (1-term fp16): vh . th, scaled by rvn*rtn
    {
        dim3 grid(SEQ/256, SEQ/128, BATCH);
        mma_gemm<1,4,1><<<grid, 256, SMEM_D>>>(v_h, t_h, nullptr,
                                               HDIM, SEQ,
                                               (long)SEQ*HDIM, (long)SEQ*HDIM,
                                               (long)SEQ*SEQ,
                                               rvn, rtn, out, nullptr, nullptr);
    }
}

// round 12
// speedup vs baseline: 1.3263x; 1.3263x over previous
#include <cuda_runtime.h>
#include <cuda_fp16.h>
#include <cstdint>

// ---------------------------------------------------------------------------
// Problem constants
// ---------------------------------------------------------------------------
#define BATCH 16
#define SEQ   1024
#define VDIM  1024
#define TDIM  768
#define HDIM  512
#define MTOT  (BATCH*SEQ)

// ---------------------------------------------------------------------------
// Scratch (device globals — allocation is forbidden)
// ---------------------------------------------------------------------------
__device__ __align__(256) __half g_vis_h[(size_t)MTOT*VDIM];
__device__ __align__(256) __half g_txt_h[(size_t)MTOT*TDIM];
__device__ __align__(256) __half g_Wv_h[(size_t)HDIM*VDIM];
__device__ __align__(256) __half g_Wv_l[(size_t)HDIM*VDIM];
__device__ __align__(256) __half g_Wt_h[(size_t)HDIM*TDIM];
__device__ __align__(256) __half g_Wt_l[(size_t)HDIM*TDIM];
__device__ __align__(256) __half g_v_h[(size_t)MTOT*HDIM];
__device__ __align__(256) __half g_t_h[(size_t)MTOT*HDIM];
__device__ float g_rvn[MTOT], g_rtn[MTOT];   // RECIPROCAL norms

// ---------------------------------------------------------------------------
// Helpers
// ---------------------------------------------------------------------------
__device__ __forceinline__ uint32_t smem_u32(const void* p) {
    uint32_t a;
    asm("{ .reg .u64 t; cvta.to.shared.u64 t, %1; cvt.u32.u64 %0, t; }"
        : "=r"(a) : "l"(p));
    return a;
}

__device__ __forceinline__ void cp_async16(uint32_t d, const void* g) {
    asm volatile("cp.async.cg.shared.global [%0], [%1], 16;\n"
                 :: "r"(d), "l"(__cvta_generic_to_global(g)) : "memory");
}
__device__ __forceinline__ void cp_commit() {
    asm volatile("cp.async.commit_group;\n" ::: "memory");
}
template <int N>
__device__ __forceinline__ void cp_wait() {
    asm volatile("cp.async.wait_group %0;\n" :: "n"(N) : "memory");
}

__device__ __forceinline__ void ldsm4(uint32_t* r, uint32_t a) {
    asm volatile("ldmatrix.sync.aligned.m8n8.x4.shared.b16 {%0,%1,%2,%3}, [%4];\n"
                 : "=r"(r[0]), "=r"(r[1]), "=r"(r[2]), "=r"(r[3]) : "r"(a));
}

__device__ __forceinline__ void mma16816(float* c, const uint32_t* a,
                                         const uint32_t* b) {
    asm volatile(
        "mma.sync.aligned.m16n8k16.row.col.f32.f16.f16.f32 "
        "{%0,%1,%2,%3}, {%4,%5,%6,%7}, {%8,%9}, {%0,%1,%2,%3};\n"
        : "+f"(c[0]), "+f"(c[1]), "+f"(c[2]), "+f"(c[3])
        : "r"(a[0]), "r"(a[1]), "r"(a[2]), "r"(a[3]), "r"(b[0]), "r"(b[1]));
}

__device__ __forceinline__ uint32_t pack2h(__half a, __half b) {
    __half2 t = __halves2half2(a, b);
    return *reinterpret_cast<uint32_t*>(&t);
}

// Swizzled smem offset: 64B rows (32 halfs), 4 x 16B chunks per row.
__device__ __forceinline__ uint32_t swoff(int row, int chunk) {
    int c2 = (chunk ^ (row & 3) ^ ((row >> 2) & 1)) & 3;
    return (uint32_t)(row * 64 + (c2 << 4));
}

// ---------------------------------------------------------------------------
// Projection GEMM (both modalities in one launch; blockIdx.z selects).
// C[m,n] = sum_k A[m,k]*(Wh[n,k]+Wl[n,k]) + bias[n]   (2-term fp16 split)
// Block 128x128, BK=32, 8 warps (2x4), warp tile 64x32, 4-stage cp.async.
// Epilogue: +bias, round to fp16, store hi only.
// ---------------------------------------------------------------------------
#define P_STG 24576            // A 8K + Bh 8K + Bl 8K
#define P_STAGES 4
#define P_SMEM (P_STAGES*P_STG)

__global__ void __launch_bounds__(256, 2) proj_gemm(
    const __half* __restrict__ visA, const __half* __restrict__ WvH,
    const __half* __restrict__ WvL,  const float* __restrict__ bV,
    __half* __restrict__ outV,
    const __half* __restrict__ txtA, const __half* __restrict__ WtH,
    const __half* __restrict__ WtL,  const float* __restrict__ bT,
    __half* __restrict__ outT)
{
    constexpr uint32_t OFF_BH = 8192, OFF_BL = 16384;
    extern __shared__ __align__(16) char smem[];

    const int tid  = threadIdx.x;
    const int lane = tid & 31;
    const int wid  = tid >> 5;
    const int wm   = wid >> 2;
    const int wn   = wid & 3;
    const int m0   = blockIdx.y * 128;
    const int n0   = blockIdx.x * 128;

    const int z = blockIdx.z;
    const int K = z ? TDIM : VDIM;
    const __half* Abh = (z ? txtA : visA) + (long)m0 * K;
    const __half* Bbh = (z ? WtH : WvH) + (long)n0 * K;
    const __half* Bbl = (z ? WtL : WvL) + (long)n0 * K;
    const float*  bias = z ? bT : bV;
    __half* Ch = z ? outT : outV;

    const uint32_t smb = smem_u32(smem);

    auto load_stage = [&](int kt, int slot) {
        const int k0 = kt * 32;
        const uint32_t sb = smb + slot * P_STG;
        #pragma unroll
        for (int h = 0; h < 2; h++) {
            int idx = tid + h * 256;
            int row = idx >> 2, kc = idx & 3;
            uint32_t off = swoff(row, kc);
            long g = (long)row * K + k0 + kc * 8;
            cp_async16(sb + off,          Abh + g);
            cp_async16(sb + OFF_BH + off, Bbh + g);
            cp_async16(sb + OFF_BL + off, Bbl + g);
        }
    };

    #pragma unroll
    for (int s = 0; s < P_STAGES - 1; s++) { load_stage(s, s); cp_commit(); }

    float acc[4][4][4];
    #pragma unroll
    for (int i = 0; i < 4; i++)
        #pragma unroll
        for (int j = 0; j < 4; j++)
            #pragma unroll
            for (int q = 0; q < 4; q++) acc[i][j][q] = 0.0f;

    const int a_r = lane & 15;
    const int a_c = lane >> 4;
    const int b_r = (lane & 7) | ((lane & 16) >> 1);
    const int b_c = (lane >> 3) & 1;

    const int T = K / 32;
    for (int kt = 0; kt < T; kt++) {
        cp_wait<P_STAGES - 2>();
        __syncthreads();
        if (kt + P_STAGES - 1 < T) load_stage(kt + P_STAGES - 1, (kt + P_STAGES - 1) % P_STAGES);
        cp_commit();

        const uint32_t st = smb + (kt % P_STAGES) * P_STG;

        #pragma unroll
        for (int s2 = 0; s2 < 2; s2++) {
            uint32_t afr[4][4];
            #pragma unroll
            for (int i = 0; i < 4; i++)
                ldsm4(afr[i], st + swoff(wm * 64 + i * 16 + a_r, s2 * 2 + a_c));
            uint32_t bf[4][2];
            #pragma unroll
            for (int jp = 0; jp < 2; jp++) {
                uint32_t r4[4];
                ldsm4(r4, st + OFF_BH + swoff(wn * 32 + jp * 16 + b_r, s2 * 2 + b_c));
                bf[jp*2][0] = r4[0]; bf[jp*2][1] = r4[1];
                bf[jp*2+1][0] = r4[2]; bf[jp*2+1][1] = r4[3];
            }
            #pragma unroll
            for (int i = 0; i < 4; i++)
                #pragma unroll
                for (int j = 0; j < 4; j++)
                    mma16816(acc[i][j], afr[i], bf[j]);
            // Bl (reuse A fragments)
            #pragma unroll
            for (int jp = 0; jp < 2; jp++) {
                uint32_t r4[4];
                ldsm4(r4, st + OFF_BL + swoff(wn * 32 + jp * 16 + b_r, s2 * 2 + b_c));
                bf[jp*2][0] = r4[0]; bf[jp*2][1] = r4[1];
                bf[jp*2+1][0] = r4[2]; bf[jp*2+1][1] = r4[3];
            }
            #pragma unroll
            for (int i = 0; i < 4; i++)
                #pragma unroll
                for (int j = 0; j < 4; j++)
                    mma16816(acc[i][j], afr[i], bf[j]);
        }
    }

    // epilogue: +bias, fp16 hi only
    #pragma unroll
    for (int i = 0; i < 4; i++) {
        long r0 = m0 + wm * 64 + i * 16 + (lane >> 2);
        #pragma unroll
        for (int j = 0; j < 4; j++) {
            int cc = n0 + wn * 32 + j * 8 + 2 * (lane & 3);
            float bx = bias[cc], by = bias[cc + 1];
            #pragma unroll
            for (int h = 0; h < 2; h++) {
                long row = r0 + h * 8;
                float x = acc[i][j][h*2 + 0] + bx;
                float y = acc[i][j][h*2 + 1] + by;
                *reinterpret_cast<uint32_t*>(Ch + row * HDIM + cc) =
                    pack2h(__float2half_rn(x), __float2half_rn(y));
            }
        }
    }
}

// ---------------------------------------------------------------------------
// Dots GEMM (batched cosine): C[z,m,n] = (v[z,m,:].t[z,n,:]) * rvn[m]*rtn[n]
// 1-term fp16. Block 128x128, warp 64x32, 4-stage cp.async.
// ---------------------------------------------------------------------------
#define D_STG 16384            // A 8K + B 8K
#define D_STAGES 4
#define D_SMEM (D_STAGES*D_STG)

__global__ void __launch_bounds__(256, 2) dots_gemm(
    const __half* __restrict__ Vp, const __half* __restrict__ Tp,
    const float* __restrict__ rvn, const float* __restrict__ rtn,
    float* __restrict__ Cf)
{
    constexpr uint32_t OFF_B = 8192;
    extern __shared__ __align__(16) char smem[];

    const int tid  = threadIdx.x;
    const int lane = tid & 31;
    const int wid  = tid >> 5;
    const int wm   = wid >> 2;
    const int wn   = wid & 3;
    const int z    = blockIdx.z;
    const int m0   = blockIdx.y * 128;
    const int n0   = blockIdx.x * 128;

    const __half* Ab = Vp + (long)z * SEQ * HDIM + (long)m0 * HDIM;
    const __half* Bb = Tp + (long)z * SEQ * HDIM + (long)n0 * HDIM;

    const uint32_t smb = smem_u32(smem);

    auto load_stage = [&](int kt, int slot) {
        const int k0 = kt * 32;
        const uint32_t sb = smb + slot * D_STG;
        #pragma unroll
        for (int h = 0; h < 2; h++) {
            int idx = tid + h * 256;
            int row = idx >> 2, kc = idx & 3;
            uint32_t off = swoff(row, kc);
            long g = (long)row * HDIM + k0 + kc * 8;
            cp_async16(sb + off,         Ab + g);
            cp_async16(sb + OFF_B + off, Bb + g);
        }
    };

    #pragma unroll
    for (int s = 0; s < D_STAGES - 1; s++) { load_stage(s, s); cp_commit(); }

    float acc[4][4][4];
    #pragma unroll
    for (int i = 0; i < 4; i++)
        #pragma unroll
        for (int j = 0; j < 4; j++)
            #pragma unroll
            for (int q = 0; q < 4; q++) acc[i][j][q] = 0.0f;

    const int a_r = lane & 15;
    const int a_c = lane >> 4;
    const int b_r = (lane & 7) | ((lane & 16) >> 1);
    const int b_c = (lane >> 3) & 1;

    const int T = HDIM / 32;   // 16
    for (int kt = 0; kt < T; kt++) {
        cp_wait<D_STAGES - 2>();
        __syncthreads();
        if (kt + D_STAGES - 1 < T) load_stage(kt + D_STAGES - 1, (kt + D_STAGES - 1) % D_STAGES);
        cp_commit();

        const uint32_t st = smb + (kt % D_STAGES) * D_STG;

        #pragma unroll
        for (int s2 = 0; s2 < 2; s2++) {
            uint32_t afr[4][4];
            #pragma unroll
            for (int i = 0; i < 4; i++)
                ldsm4(afr[i], st + swoff(wm * 64 + i * 16 + a_r, s2 * 2 + a_c));
            uint32_t bf[4][2];
            #pragma unroll
            for (int jp = 0; jp < 2; jp++) {
                uint32_t r4[4];
                ldsm4(r4, st + OFF_B + swoff(wn * 32 + jp * 16 + b_r, s2 * 2 + b_c));
                bf[jp*2][0] = r4[0]; bf[jp*2][1] = r4[1];
                bf[jp*2+1][0] = r4[2]; bf[jp*2+1][1] = r4[3];
            }
            #pragma unroll
            for (int i = 0; i < 4; i++)
                #pragma unroll
                for (int j = 0; j < 4; j++)
                    mma16816(acc[i][j], afr[i], bf[j]);
        }
    }

    // epilogue: scale by reciprocal norms
    #pragma unroll
    for (int i = 0; i < 4; i++) {
        int r0 = m0 + wm * 64 + i * 16 + (lane >> 2);
        float rv0 = rvn[z * SEQ + r0];
        float rv1 = rvn[z * SEQ + r0 + 8];
        #pragma unroll
        for (int j = 0; j < 4; j++) {
            int cc = n0 + wn * 32 + j * 8 + 2 * (lane & 3);
            float rt0 = rtn[z * SEQ + cc], rt1 = rtn[z * SEQ + cc + 1];
            float2 o0, o1;
            o0.x = acc[i][j][0] * (rv0 * rt0);
            o0.y = acc[i][j][1] * (rv0 * rt1);
            o1.x = acc[i][j][2] * (rv1 * rt0);
            o1.y = acc[i][j][3] * (rv1 * rt1);
            float* p = Cf + (long)z * SEQ * SEQ + (long)r0 * SEQ + cc;
            *reinterpret_cast<float2*>(p)            = o0;
            *reinterpret_cast<float2*>(p + 8L * SEQ) = o1;
        }
    }
}

// ---------------------------------------------------------------------------
// Fused preprocessing: one launch covers
//  seg0: vis -> fp16 hi           seg1: txt -> fp16 hi
//  seg2: Wv  -> fp16 hi+lo        seg3: Wt  -> fp16 hi+lo
// ---------------------------------------------------------------------------
#define N4_VIS (MTOT*(VDIM/4))
#define N4_TXT (MTOT*(TDIM/4))
#define N4_WV  (HDIM*(VDIM/4))
#define N4_WT  (HDIM*(TDIM/4))
#define N4_ALL (N4_VIS + N4_TXT + N4_WV + N4_WT)

__device__ __forceinline__ uint2 cvt4(float4 v) {
    return make_uint2(pack2h(__float2half_rn(v.x), __float2half_rn(v.y)),
                      pack2h(__float2half_rn(v.z), __float2half_rn(v.w)));
}
__device__ __forceinline__ void split4(float4 v, uint2& h, uint2& l) {
    __half h0 = __float2half_rn(v.x), h1 = __float2half_rn(v.y);
    __half h2 = __float2half_rn(v.z), h3 = __float2half_rn(v.w);
    h = make_uint2(pack2h(h0, h1), pack2h(h2, h3));
    l = make_uint2(pack2h(__float2half_rn(v.x - __half2float(h0)),
                          __float2half_rn(v.y - __half2float(h1))),
                   pack2h(__float2half_rn(v.z - __half2float(h2)),
                          __float2half_rn(v.w - __half2float(h3))));
}

__global__ void prep_kernel(
    const float4* __restrict__ vis, const float4* __restrict__ txt,
    const float4* __restrict__ Wv,  const float4* __restrict__ Wt,
    uint2* __restrict__ vis_h, uint2* __restrict__ txt_h,
    uint2* __restrict__ Wv_h, uint2* __restrict__ Wv_l,
    uint2* __restrict__ Wt_h, uint2* __restrict__ Wt_l)
{
    int i = blockIdx.x * blockDim.x + threadIdx.x;
    if (i < N4_VIS) {
        vis_h[i] = cvt4(vis[i]);
    } else if ((i -= N4_VIS) < N4_TXT) {
        txt_h[i] = cvt4(txt[i]);
    } else if ((i -= N4_TXT) < N4_WV) {
        uint2 h, l; split4(Wv[i], h, l);
        Wv_h[i] = h; Wv_l[i] = l;
    } else if ((i -= N4_WV) < N4_WT) {
        uint2 h, l; split4(Wt[i], h, l);
        Wt_h[i] = h; Wt_l[i] = l;
    }
}

// ---------------------------------------------------------------------------
// Reciprocal row L2 norms (hi-only input is accurate to ~4e-5 in the norm).
// One warp per row; rows [0,MTOT) -> v, [MTOT,2*MTOT) -> t.
// ---------------------------------------------------------------------------
__global__ void norms_kernel(const __half* __restrict__ V,
                             const __half* __restrict__ Tt,
                             float* __restrict__ rvn, float* __restrict__ rtn)
{
    int row  = blockIdx.x * blockDim.y + threadIdx.y;
    int lane = threadIdx.x;
    const __half* src;
    float* dst;
    int r;
    if (row < MTOT) { src = V + (long)row * HDIM; dst = rvn; r = row; }
    else { r = row - MTOT; src = Tt + (long)r * HDIM; dst = rtn; }
    float s = 0.0f;
    #pragma unroll
    for (int i = lane * 4; i < HDIM; i += 128) {
        uint2 hu = *reinterpret_cast<const uint2*>(src + i);
        __half2 h01 = *reinterpret_cast<const __half2*>(&hu.x);
        __half2 h23 = *reinterpret_cast<const __half2*>(&hu.y);
        float x0 = __low2float(h01),  x1 = __high2float(h01);
        float x2 = __low2float(h23),  x3 = __high2float(h23);
        s += x0*x0 + x1*x1 + x2*x2 + x3*x3;
    }
    #pragma unroll
    for (int o = 16; o > 0; o >>= 1) s += __shfl_xor_sync(0xffffffffu, s, o);
    if (lane == 0) dst[r] = rsqrtf(fmaxf(s, 1e-16f));
}

// ---------------------------------------------------------------------------
extern "C" void kernel_launch(void* const* d_in, const int* in_sizes, int n_in,
                              void* d_out, int out_size)
{
    const float* vis = (const float*)d_in[0];   // [16,1024,1024]
    const float* txt = (const float*)d_in[1];   // [16,1024,768]
    const float* Wv  = (const float*)d_in[2];   // [512,1024]
    const float* bv  = (const float*)d_in[3];   // [512]
    const float* Wt  = (const float*)d_in[4];   // [512,768]
    const float* bt  = (const float*)d_in[5];   // [512]
    float* out = (float*)d_out;                 // [16,1024,1024]

    __half *vis_h, *txt_h, *Wv_h, *Wv_l, *Wt_h, *Wt_l, *v_h, *t_h;
    float *rvn, *rtn;
    cudaGetSymbolAddress((void**)&vis_h, g_vis_h);
    cudaGetSymbolAddress((void**)&txt_h, g_txt_h);
    cudaGetSymbolAddress((void**)&Wv_h,  g_Wv_h);
    cudaGetSymbolAddress((void**)&Wv_l,  g_Wv_l);
    cudaGetSymbolAddress((void**)&Wt_h,  g_Wt_h);
    cudaGetSymbolAddress((void**)&Wt_l,  g_Wt_l);
    cudaGetSymbolAddress((void**)&v_h,   g_v_h);
    cudaGetSymbolAddress((void**)&t_h,   g_t_h);
    cudaGetSymbolAddress((void**)&rvn,   g_rvn);
    cudaGetSymbolAddress((void**)&rtn,   g_rtn);

    (void)cudaFuncSetAttribute((const void*)proj_gemm,
                               cudaFuncAttributeMaxDynamicSharedMemorySize, P_SMEM);
    (void)cudaFuncSetAttribute((const void*)dots_gemm,
                               cudaFuncAttributeMaxDynamicSharedMemorySize, D_SMEM);

    // 1) Fused preprocessing (1 launch)
    prep_kernel<<<(N4_ALL + 255) / 256, 256>>>(
        (const float4*)vis, (const float4*)txt,
        (const float4*)Wv, (const float4*)Wt,
        (uint2*)vis_h, (uint2*)txt_h,
        (uint2*)Wv_h, (uint2*)Wv_l, (uint2*)Wt_h, (uint2*)Wt_l);

    // 2) Both projections, one launch (z=0: visual K=1024, z=1: text K=768)
    {
        dim3 grid(HDIM / 128, MTOT / 128, 2);
        proj_gemm<<<grid, 256, P_SMEM>>>(vis_h, Wv_h, Wv_l, bv, v_h,
                                         txt_h, Wt_h, Wt_l, bt, t_h);
    }

    // 3) Reciprocal row norms, one launch (v rows then t rows)
    {
        dim3 blk(32, 8), grid(2 * MTOT / 8);
        norms_kernel<<<grid, blk>>>(v_h, t_h, rvn, rtn);
    }

    // 4) Batched cosine GEMM
    {
        dim3 grid(SEQ / 128, SEQ / 128, BATCH);
        dots_gemm<<<grid, 256, D_SMEM>>>(v_h, t_h, rvn, rtn, out);
    }
}